// round 16
// baseline (speedup 1.0000x reference)
#include <cuda_runtime.h>
#include <cstdint>

// CensusLoss: 5x5 census hamming, reflect pad, mean. (8,3,512,512) fp32 in [0,1).
// Total = 2 * sum_x sum_{d in D12} f(x, R(x+d)) + C (boundary strip correction).
// Packed f32x2 diffs + PRMT sign-gather + DP4A accumulation (3 SASS/comparison).

typedef unsigned long long ull;

#define HH   512
#define WW   512
#define NIMG 24
#define TW   128
#define TH2  32                // tile height (4 center rows per warp x 8 warps)
#define NROW 34                // smem rows: TH2 + 2 halo below
#define NCOL 132               // halo cols col0-2 .. col0+129
#define ROWB 1088              // row stride bytes (132*8=1056, padded, 16B multiple)
#define NELEM 6291456.0
#define MAIN_BLOCKS ((WW/TW)*(HH/TH2)*NIMG)    // 1536
#define TOTAL_BLOCKS (MAIN_BLOCKS + 4*NIMG)    // + 96 strip blocks
#define STRIP 4080

__device__ unsigned g_acc = 0;
__device__ unsigned g_cnt = 0;

__device__ __forceinline__ int refl(int i, int n) {
    i = (i < 0) ? -i : i;
    return (i >= n) ? (2 * n - 2 - i) : i;
}
__device__ __forceinline__ int sw8(int o) { return o ^ ((o >> 3) & 0x70); }

__device__ __forceinline__ ull addx2(ull a, ull b) {
    ull d; asm("add.rn.f32x2 %0, %1, %2;" : "=l"(d) : "l"(a), "l"(b)); return d;
}
__device__ __forceinline__ ull negx2(ull a) {
    ull d; asm("mul.rn.f32x2 %0, %1, %2;" : "=l"(d) : "l"(a), "l"(0xBF800000BF800000ULL));
    return d;
}
__device__ __forceinline__ unsigned xs(ull d) {           // sign(lo)^sign(hi) at bit31
    return (unsigned)(d >> 32) ^ (unsigned)d;
}
__device__ __forceinline__ unsigned sb2(float a, float b, float c, float d) {
    return (unsigned)(__float_as_int(a - b) ^ __float_as_int(c - d)) >> 31;
}

// two comparisons -> one dp4a step: acc += -(cmpA) - (cmpB)
__device__ __forceinline__ void cmp2(int& acc, ull ya, ull nca, ull yb, ull ncb) {
    unsigned x0 = xs(addx2(ya, nca));
    unsigned x1 = xs(addx2(yb, ncb));
    unsigned u;
    asm("prmt.b32 %0, %1, %2, 0xFB;" : "=r"(u) : "r"(x0), "r"(x1));  // [sA,sB,.,.]
    acc = __dp4a((int)u, 0x0101, acc);   // bytes 0,1 weighted; 0xFF(s8)=-1
}

__global__ __launch_bounds__(256, 6)
void census_kernel(const float* __restrict__ pred, const float* __restrict__ gt,
                   float* __restrict__ out)
{
    __shared__ __align__(16) char smem[NROW * ROWB];   // interleaved (p,g) float2, swizzled
    __shared__ int wsum[8];

    const int tid = threadIdx.x;
    const int img = blockIdx.z;
    const float* __restrict__ p = pred + (size_t)img * HH * WW;
    const float* __restrict__ g = gt   + (size_t)img * HH * WW;

    int contrib = 0;

    if (blockIdx.y < HH / TH2) {
        const int row0 = blockIdx.y * TH2;
        const int col0 = blockIdx.x * TW;

        // ---------------- halo load (interleaved + swizzled) ----------------
        const bool interior = (blockIdx.x > 0) && (blockIdx.x < 3) &&
                              (blockIdx.y < HH / TH2 - 1);
        if (interior) {
            for (int idx = tid; idx < NROW * 66; idx += 256) {
                int lr = idx / 66;
                int l2 = idx - lr * 66;
                const float* rp = p + (row0 + lr) * WW + (col0 - 2) + 2 * l2;
                const float* rg = g + (row0 + lr) * WW + (col0 - 2) + 2 * l2;
                float2 pv = *(const float2*)rp;
                float2 gv = *(const float2*)rg;
                char* d = smem + lr * ROWB + sw8(l2 * 16);
                *(float2*)(d)     = make_float2(pv.x, gv.x);
                *(float2*)(d + 8) = make_float2(pv.y, gv.y);
            }
        } else {
            for (int idx = tid; idx < NROW * NCOL; idx += 256) {
                int lr = idx / NCOL;
                int lc = idx - lr * NCOL;
                int r = refl(row0 + lr, HH);
                int c = refl(col0 + lc - 2, WW);
                *(float2*)(smem + lr * ROWB + sw8(lc * 8)) =
                    make_float2(p[r * WW + c], g[r * WW + c]);
            }
        }
        __syncthreads();

        // ------- rolling census: warp = 128 cols x 4 center rows, thread = 4 px -------
        const int ty0  = (tid >> 5) * 4;
        const int lane = tid & 31;
        const int lb   = lane * 32;                 // byte base: float2 col index lane*4
        const int b0 = sw8(lb +  0), b1 = sw8(lb + 16),
                  b2 = sw8(lb + 32), b3 = sw8(lb + 48);

        int acc0 = 0, acc1 = 0;                     // dp4a chains (negative counts)
        ull A[8], B[8], C[8], nc0, nc1, nc2, nc3;

#define LDROW(r, R) { const char* rp_ = smem + (r) * ROWB;              \
        ulonglong2 u0 = *(const ulonglong2*)(rp_ + b0);                 \
        ulonglong2 u1 = *(const ulonglong2*)(rp_ + b1);                 \
        ulonglong2 u2 = *(const ulonglong2*)(rp_ + b2);                 \
        ulonglong2 u3 = *(const ulonglong2*)(rp_ + b3);                 \
        R[0]=u0.x; R[1]=u0.y; R[2]=u1.x; R[3]=u1.y;                     \
        R[4]=u2.x; R[5]=u2.y; R[6]=u3.x; R[7]=u3.y; }

        // centers at window cols 2..5; dr0 offsets (0,1),(0,2): j=k+3, k+4
#define CENTERS_DR0(T) {                                                \
        nc0 = negx2(T[2]); nc1 = negx2(T[3]);                           \
        nc2 = negx2(T[4]); nc3 = negx2(T[5]);                           \
        cmp2(acc0, T[3], nc0, T[4], nc0);                               \
        cmp2(acc1, T[4], nc1, T[5], nc1);                               \
        cmp2(acc0, T[5], nc2, T[6], nc2);                               \
        cmp2(acc1, T[6], nc3, T[7], nc3); }

        // full row vs centers: dc=-2..2 -> j = k + dc + 2
#define CMPROW(Y) {                                                     \
        _Pragma("unroll")                                               \
        for (int dc = 0; dc < 5; ++dc) {                                \
            cmp2(acc0, Y[dc + 0], nc0, Y[dc + 1], nc1);                 \
            cmp2(acc1, Y[dc + 2], nc2, Y[dc + 3], nc3);                 \
        } }

        LDROW(ty0 + 0, A); LDROW(ty0 + 1, B);
        CENTERS_DR0(A); CMPROW(B); LDROW(ty0 + 2, C); CMPROW(C);
        CENTERS_DR0(B); CMPROW(C); LDROW(ty0 + 3, A); CMPROW(A);
        CENTERS_DR0(C); CMPROW(A); LDROW(ty0 + 4, B); CMPROW(B);
        CENTERS_DR0(A); CMPROW(B); LDROW(ty0 + 5, C); CMPROW(C);

        contrib = -2 * (acc0 + acc1);               // counts were accumulated as -1s
#undef LDROW
#undef CENTERS_DR0
#undef CMPROW
    } else {
        // ---------------- boundary correction strip ----------------
        const int DR[12] = {0, 0, 1, 1, 1, 1, 1, 2, 2, 2, 2, 2};
        const int DC[12] = {1, 2,-2,-1, 0, 1, 2,-2,-1, 0, 1, 2};
        for (int s = blockIdx.x * 256 + tid; s < STRIP; s += 1024) {
            int r, c;
            if (s < 2048) {
                int ri = s >> 9;
                r = (ri < 2) ? ri : (508 + ri);
                c = s & 511;
            } else {
                int t2 = s - 2048;
                int ci = t2 & 3;
                c = (ci < 2) ? ci : (508 + ci);
                r = 2 + (t2 >> 2);
            }
            const float pcv = p[r * WW + c];
            const float gcv = g[r * WW + c];
            #pragma unroll
            for (int o = 0; o < 12; ++o) {
                const int dr = DR[o], dc = DC[o];
                int rm = r - dr, cm = c - dc;
                if ((unsigned)rm >= HH || (unsigned)cm >= WW) {
                    int rr = refl(rm, HH) * WW + refl(cm, WW);
                    contrib += (int)sb2(p[rr], pcv, g[rr], gcv);
                }
                int rp2 = r + dr, cp = c + dc;
                if ((unsigned)rp2 >= HH || (unsigned)cp >= WW) {
                    int rr = refl(rp2, HH) * WW + refl(cp, WW);
                    contrib -= (int)sb2(p[rr], pcv, g[rr], gcv);
                }
            }
        }
    }

    // ---------------- exact integer reduction + last-block finalize ----------------
    contrib = __reduce_add_sync(0xffffffffu, contrib);
    if ((tid & 31) == 0) wsum[tid >> 5] = contrib;
    __syncthreads();

    if (tid == 0) {
        int s = 0;
        #pragma unroll
        for (int w = 0; w < 8; ++w) s += wsum[w];
        atomicAdd(&g_acc, (unsigned)s);
        __threadfence();
        unsigned t = atomicAdd(&g_cnt, 1u);
        if (t == TOTAL_BLOCKS - 1) {
            __threadfence();
            unsigned total = atomicExch(&g_acc, 0u);   // read + reset for next replay
            out[0] = (float)((double)total / NELEM);
            g_cnt = 0;
        }
    }
}

extern "C" void kernel_launch(void* const* d_in, const int* in_sizes, int n_in,
                              void* d_out, int out_size)
{
    const float* pred = (const float*)d_in[0];
    const float* gt   = (const float*)d_in[1];
    float* out        = (float*)d_out;

    dim3 grid(WW / TW, HH / TH2 + 1, NIMG);   // (4, 17, 24): y==16 -> strip blocks
    census_kernel<<<grid, 256>>>(pred, gt, out);
}

// round 17
// speedup vs baseline: 1.9520x; 1.9520x over previous
#include <cuda_runtime.h>
#include <cstdint>

// CensusLoss: 5x5 census hamming, reflect pad, mean. (8,3,512,512) fp32 in [0,1).
// Total = 2 * sum_x sum_{d in D12} f(x, R(x+d)) + C (boundary strip correction).
// Packed f32x2 core, p/g-interleaved swizzled smem, vertical register rolling.
// This round: single resident wave (864 blocks; main blocks do 2 tiles) + LDS hoist.

typedef unsigned long long ull;

#define HH   512
#define WW   512
#define NIMG 24
#define TW   128
#define TH2  32                // tile height (4 center rows per warp x 8 warps)
#define NROW 34                // smem rows: TH2 + 2 halo below
#define NCOL 132               // halo cols col0-2 .. col0+129
#define ROWB 1088              // row stride bytes (132*8=1056, padded, 16B multiple)
#define NELEM 6291456.0
#define NTILE 1536             // 4*16*24 main tiles
#define MAINB 768              // main blocks (2 tiles each)
#define TOTAL_BLOCKS 864       // 768 main + 96 strip  (single wave: <= 6*148)
#define STRIP 4080

__device__ unsigned g_acc = 0;
__device__ unsigned g_cnt = 0;

__device__ __forceinline__ int refl(int i, int n) {
    i = (i < 0) ? -i : i;
    return (i >= n) ? (2 * n - 2 - i) : i;
}
__device__ __forceinline__ int sw8(int o) { return o ^ ((o >> 3) & 0x70); }

__device__ __forceinline__ ull addx2(ull a, ull b) {
    ull d; asm("add.rn.f32x2 %0, %1, %2;" : "=l"(d) : "l"(a), "l"(b)); return d;
}
__device__ __forceinline__ ull negx2(ull a) {
    ull d; asm("mul.rn.f32x2 %0, %1, %2;" : "=l"(d) : "l"(a), "l"(0xBF800000BF800000ULL));
    return d;
}
__device__ __forceinline__ unsigned xs(ull d) {           // sign(lo)^sign(hi) at bit31
    return (unsigned)(d >> 32) ^ (unsigned)d;
}
__device__ __forceinline__ unsigned sb2(float a, float b, float c, float d) {
    return (unsigned)(__float_as_int(a - b) ^ __float_as_int(c - d)) >> 31;
}

__global__ __launch_bounds__(256, 6)
void census_kernel(const float* __restrict__ pred, const float* __restrict__ gt,
                   float* __restrict__ out)
{
    __shared__ __align__(16) char smem[NROW * ROWB];   // interleaved (p,g) float2, swizzled
    __shared__ int wsum[8];

    const int tid = threadIdx.x;
    const int bid = blockIdx.x;

    int contrib = 0;

    if (bid < MAINB) {
        // ---------------- two tiles per block (tiles 2*bid, 2*bid+1) ----------------
        unsigned a0 = 0, a1 = 0, a2 = 0, a3 = 0;

        #pragma unroll 1
        for (int it = 0; it < 2; ++it) {
            const int t    = 2 * bid + it;
            const int img  = t >> 6;
            const int rem  = t & 63;
            const int row0 = (rem >> 2) * TH2;
            const int col0 = (rem & 3) * TW;
            const float* __restrict__ p = pred + (size_t)img * HH * WW;
            const float* __restrict__ g = gt   + (size_t)img * HH * WW;

            if (it) __syncthreads();    // previous tile's compute done before overwrite

            const bool interior = ((rem & 3) > 0) && ((rem & 3) < 3) && ((rem >> 2) < 15);
            if (interior) {
                for (int idx = tid; idx < NROW * 66; idx += 256) {
                    int lr = idx / 66;
                    int l2 = idx - lr * 66;
                    const float* rp = p + (row0 + lr) * WW + (col0 - 2) + 2 * l2;
                    const float* rg = g + (row0 + lr) * WW + (col0 - 2) + 2 * l2;
                    float2 pv = *(const float2*)rp;
                    float2 gv = *(const float2*)rg;
                    char* d = smem + lr * ROWB + sw8(l2 * 16);
                    *(float2*)(d)     = make_float2(pv.x, gv.x);
                    *(float2*)(d + 8) = make_float2(pv.y, gv.y);
                }
            } else {
                for (int idx = tid; idx < NROW * NCOL; idx += 256) {
                    int lr = idx / NCOL;
                    int lc = idx - lr * NCOL;
                    int r = refl(row0 + lr, HH);
                    int c = refl(col0 + lc - 2, WW);
                    *(float2*)(smem + lr * ROWB + sw8(lc * 8)) =
                        make_float2(p[r * WW + c], g[r * WW + c]);
                }
            }
            __syncthreads();

            // ------- rolling census: warp = 128 cols x 4 center rows, thread = 4 px ---
            const int ty0  = (tid >> 5) * 4;
            const int lane = tid & 31;
            const int lb   = lane * 32;
            const int b0 = sw8(lb +  0), b1 = sw8(lb + 16),
                      b2 = sw8(lb + 32), b3 = sw8(lb + 48);

            ull A[8], B[8], C[8], nc0, nc1, nc2, nc3;

#define LDROW(r, R) { const char* rp_ = smem + (r) * ROWB;              \
            ulonglong2 u0 = *(const ulonglong2*)(rp_ + b0);             \
            ulonglong2 u1 = *(const ulonglong2*)(rp_ + b1);             \
            ulonglong2 u2 = *(const ulonglong2*)(rp_ + b2);             \
            ulonglong2 u3 = *(const ulonglong2*)(rp_ + b3);             \
            R[0]=u0.x; R[1]=u0.y; R[2]=u1.x; R[3]=u1.y;                 \
            R[4]=u2.x; R[5]=u2.y; R[6]=u3.x; R[7]=u3.y; }

#define CENTERS_DR0(T) {                                                \
            nc0 = negx2(T[2]); nc1 = negx2(T[3]);                       \
            nc2 = negx2(T[4]); nc3 = negx2(T[5]);                       \
            a0 += xs(addx2(T[3], nc0)) >> 31;  a0 += xs(addx2(T[4], nc0)) >> 31; \
            a1 += xs(addx2(T[4], nc1)) >> 31;  a1 += xs(addx2(T[5], nc1)) >> 31; \
            a2 += xs(addx2(T[5], nc2)) >> 31;  a2 += xs(addx2(T[6], nc2)) >> 31; \
            a3 += xs(addx2(T[6], nc3)) >> 31;  a3 += xs(addx2(T[7], nc3)) >> 31; }

#define CMPROW(Y) {                                                     \
            _Pragma("unroll")                                           \
            for (int dc = 0; dc < 5; ++dc) {                            \
                a0 += xs(addx2(Y[dc + 0], nc0)) >> 31;                  \
                a1 += xs(addx2(Y[dc + 1], nc1)) >> 31;                  \
                a2 += xs(addx2(Y[dc + 2], nc2)) >> 31;                  \
                a3 += xs(addx2(Y[dc + 3], nc3)) >> 31;                  \
            } }

            // LDROW hoisted one slot ahead of its consumer for LDS-latency cover.
            LDROW(ty0 + 0, A); LDROW(ty0 + 1, B);
            CENTERS_DR0(A); LDROW(ty0 + 2, C); CMPROW(B); CMPROW(C);
            CENTERS_DR0(B); LDROW(ty0 + 3, A); CMPROW(C); CMPROW(A);
            CENTERS_DR0(C); LDROW(ty0 + 4, B); CMPROW(A); CMPROW(B);
            CENTERS_DR0(A); LDROW(ty0 + 5, C); CMPROW(B); CMPROW(C);
#undef LDROW
#undef CENTERS_DR0
#undef CMPROW
        }
        contrib = (int)(2u * (a0 + a1 + a2 + a3));
    } else {
        // ---------------- boundary correction strip (96 blocks) ----------------
        const int sidx = bid - MAINB;          // 0..95
        const int img  = sidx >> 2;            // 4 blocks per image
        const int part = sidx & 3;
        const float* __restrict__ p = pred + (size_t)img * HH * WW;
        const float* __restrict__ g = gt   + (size_t)img * HH * WW;
        const int DR[12] = {0, 0, 1, 1, 1, 1, 1, 2, 2, 2, 2, 2};
        const int DC[12] = {1, 2,-2,-1, 0, 1, 2,-2,-1, 0, 1, 2};
        for (int s = part * 256 + tid; s < STRIP; s += 1024) {
            int r, c;
            if (s < 2048) {
                int ri = s >> 9;
                r = (ri < 2) ? ri : (508 + ri);
                c = s & 511;
            } else {
                int t2 = s - 2048;
                int ci = t2 & 3;
                c = (ci < 2) ? ci : (508 + ci);
                r = 2 + (t2 >> 2);
            }
            const float pcv = p[r * WW + c];
            const float gcv = g[r * WW + c];
            #pragma unroll
            for (int o = 0; o < 12; ++o) {
                const int dr = DR[o], dc = DC[o];
                int rm = r - dr, cm = c - dc;
                if ((unsigned)rm >= HH || (unsigned)cm >= WW) {
                    int rr = refl(rm, HH) * WW + refl(cm, WW);
                    contrib += (int)sb2(p[rr], pcv, g[rr], gcv);
                }
                int rp2 = r + dr, cp = c + dc;
                if ((unsigned)rp2 >= HH || (unsigned)cp >= WW) {
                    int rr = refl(rp2, HH) * WW + refl(cp, WW);
                    contrib -= (int)sb2(p[rr], pcv, g[rr], gcv);
                }
            }
        }
    }

    // ---------------- exact integer reduction + last-block finalize ----------------
    contrib = __reduce_add_sync(0xffffffffu, contrib);
    if ((tid & 31) == 0) wsum[tid >> 5] = contrib;
    __syncthreads();

    if (tid == 0) {
        int s = 0;
        #pragma unroll
        for (int w = 0; w < 8; ++w) s += wsum[w];
        atomicAdd(&g_acc, (unsigned)s);
        __threadfence();
        unsigned t = atomicAdd(&g_cnt, 1u);
        if (t == TOTAL_BLOCKS - 1) {
            __threadfence();
            unsigned total = atomicExch(&g_acc, 0u);   // read + reset for next replay
            out[0] = (float)((double)total / NELEM);
            g_cnt = 0;
        }
    }
}

extern "C" void kernel_launch(void* const* d_in, const int* in_sizes, int n_in,
                              void* d_out, int out_size)
{
    const float* pred = (const float*)d_in[0];
    const float* gt   = (const float*)d_in[1];
    float* out        = (float*)d_out;

    census_kernel<<<TOTAL_BLOCKS, 256>>>(pred, gt, out);
}